// round 9
// baseline (speedup 1.0000x reference)
#include <cuda_runtime.h>
#include <stdint.h>

// Problem constants (fixed by the reference problem definition)
#define FEAT_DIM 128
#define BATCH    4
#define NY       512
#define NX       512
#define NYNX     (NY * NX)
#define NPIX     (BATCH * NYNX)      // 1,048,576

#define NBUF  4        // ring buffers
#define SPX   32       // pixels per stage
#define NSTG  (NX / SPX)             // 16 stages = one full y-row per block
#define NTH   512      // 16 warps; 3 blocks/SM (smem 66KB) = 48 warps

// 4 MB scratch: winner map. INVARIANT: all-zero on entry to kernel_launch.
//  - zero at module load (device globals are zero-initialized)
//  - k_argmax writes (voxel_index + 1) via atomicMax (last-write-wins == max idx)
//  - k_gather restores every nonzero entry it consumed back to 0
__device__ int g_map[NPIX];

// ---------------------------------------------------------------------------
// cp.async helpers: 16B global->shared, src_size=0 => zero-fill (empty pixels)
// ---------------------------------------------------------------------------
__device__ __forceinline__ uint32_t smem_u32(const void* p) {
    return (uint32_t)__cvta_generic_to_shared(p);
}
__device__ __forceinline__ void cp_async16(uint32_t dst, const void* src, int src_size) {
    asm volatile("cp.async.cg.shared.global [%0], [%1], 16, %2;\n"
                 :: "r"(dst), "l"(src), "r"(src_size));
}
__device__ __forceinline__ void cp_commit() {
    asm volatile("cp.async.commit_group;\n" ::: "memory");
}
template <int N>
__device__ __forceinline__ void cp_wait() {
    asm volatile("cp.async.wait_group %0;\n" :: "n"(N) : "memory");
}

// ---------------------------------------------------------------------------
// Kernel 1: winner per pixel.  coors: [N,4] int32 (b, z, y, x)
// ---------------------------------------------------------------------------
__global__ void k_argmax_map(const int* __restrict__ coors, int n) {
    int i = (blockIdx.x * blockDim.x + threadIdx.x) * 2;
    if (i < n) {
        int4 c = reinterpret_cast<const int4*>(coors)[i];
        atomicMax(&g_map[c.x * NYNX + c.z * NX + c.w], i + 1);
    }
    if (i + 1 < n) {
        int4 c = reinterpret_cast<const int4*>(coors)[i + 1];
        atomicMax(&g_map[c.x * NYNX + c.z * NX + c.w], i + 2);
    }
}

// ---------------------------------------------------------------------------
// Kernel 2: gather + transpose. One block per (b, y): writes FULL 2KB rows
// per channel (max DRAM write locality). 16 stages of 32 pixels stream
// through a 4-buffer cp.async ring so ~3 stages of reads are always in
// flight behind each drain:
//   fill(0..3); for s: wait<pending>; sync; drain(s); sync; fill(s+4)
// Swizzle: P(xl, c) = xl*128 + ((c>>2 ^ xl) << 2) + (c&3), xl = x % 32.
//   Fill : warp=pixel, lane=quad -> cp.async 16B, conflict-free smem dst.
//   Drain: lane=x-in-stage, quad per item -> LDS.128 + 4x coalesced STG.32.
// ---------------------------------------------------------------------------
__device__ __forceinline__ void fill_stage(const float* __restrict__ feat,
                                           float* __restrict__ buf,
                                           const int* __restrict__ vidx,
                                           int s, int warp, int lane) {
    #pragma unroll
    for (int m = 0; m < 2; m++) {
        int xl = warp * 2 + m;                     // 0..31 within stage
        int v  = vidx[s * SPX + xl];
        uint32_t dst = smem_u32(&buf[xl * FEAT_DIM + ((lane ^ xl) << 2)]);
        const float* src = feat + (size_t)(v < 0 ? 0 : v) * FEAT_DIM + lane * 4;
        cp_async16(dst, src, v < 0 ? 0 : 16);      // zfill empties
    }
    cp_commit();
}

__global__ __launch_bounds__(NTH, 3)
void k_gather(const float* __restrict__ feat, float* __restrict__ out) {
    __shared__ float buf[NBUF][SPX * FEAT_DIM];    // 4 x 16 KB ring
    __shared__ int   vidx[NX];                     // 2 KB

    int blk = blockIdx.x;              // 0 .. BATCH*NY-1
    int y   = blk & (NY - 1);
    int b   = blk >> 9;

    int t = threadIdx.x, warp = t >> 5, lane = t & 31;

    {   // one pixel per thread: stage vidx, restore map invariant
        int idx = b * NYNX + y * NX + t;
        int v = g_map[idx];
        vidx[t] = v - 1;               // -1 if empty
        if (v) g_map[idx] = 0;
    }
    __syncthreads();

    // Prologue: fill stages 0..3
    #pragma unroll
    for (int s = 0; s < NBUF; s++)
        fill_stage(feat, buf[s], vidx, s, warp, lane);

    size_t rowbase = (size_t)b * FEAT_DIM * NYNX + (size_t)y * NX;

    #pragma unroll
    for (int s = 0; s < NSTG; s++) {
        // groups committed so far: min(NSTG, s+4); need group s complete
        constexpr int LAST = NSTG - 1;
        if      (s <= LAST - 3) cp_wait<3>();
        else if (s == LAST - 2) cp_wait<2>();
        else if (s == LAST - 1) cp_wait<1>();
        else                    cp_wait<0>();
        __syncthreads();

        const float* bs = buf[s & (NBUF - 1)];
        #pragma unroll
        for (int m = 0; m < 2; m++) {
            int q = warp * 2 + m;                  // channel quad 0..31
            float4 val = *reinterpret_cast<const float4*>(
                &bs[lane * FEAT_DIM + ((q ^ lane) << 2)]);  // LDS.128
            size_t o = rowbase + (size_t)(4 * q) * NYNX + s * SPX + lane;
            out[o]            = val.x;             // 4 x 128B coalesced STG
            out[o +     NYNX] = val.y;
            out[o + 2 * NYNX] = val.z;
            out[o + 3 * NYNX] = val.w;
        }
        __syncthreads();                           // buffer free for refill

        if (s + NBUF < NSTG)
            fill_stage(feat, buf[s & (NBUF - 1)], vidx, s + NBUF, warp, lane);
    }
}

// ---------------------------------------------------------------------------
extern "C" void kernel_launch(void* const* d_in, const int* in_sizes, int n_in,
                              void* d_out, int out_size) {
    const float* feat  = (const float*)d_in[0];
    const int*   coors = (const int*)d_in[1];
    float*       out   = (float*)d_out;

    int n = in_sizes[0] / FEAT_DIM;   // number of voxels

    // 1) winner per pixel (map is all-zero by invariant)
    k_argmax_map<<<(n / 2 + 255) / 256, 256>>>(coors, n);
    // 2) gather + transpose full output (and restore map to zero)
    k_gather<<<BATCH * NY, NTH>>>(feat, out);
}

// round 10
// speedup vs baseline: 1.0150x; 1.0150x over previous
#include <cuda_runtime.h>
#include <stdint.h>

// Problem constants (fixed by the reference problem definition)
#define FEAT_DIM 128
#define BATCH    4
#define NY       512
#define NX       512
#define NYNX     (NY * NX)
#define NPIX     (BATCH * NYNX)      // 1,048,576

#define XT    128      // x-tile per block (4 stages of 32)
#define SPX   32       // pixels per stage
#define NSTG  (XT / SPX)             // 4 stages
#define NBUF  3        // ring buffers: smem ~50KB -> 4 blocks/SM = 64 warps
#define NTH   512      // 16 warps

// 4 MB scratch: winner map. INVARIANT: all-zero on entry to kernel_launch.
//  - zero at module load (device globals are zero-initialized)
//  - k_argmax writes (voxel_index + 1) via atomicMax (last-write-wins == max idx)
//  - k_gather restores every nonzero entry it consumed back to 0
__device__ int g_map[NPIX];

// ---------------------------------------------------------------------------
// cp.async helpers: 16B global->shared, src_size=0 => zero-fill (empty pixels)
// ---------------------------------------------------------------------------
__device__ __forceinline__ uint32_t smem_u32(const void* p) {
    return (uint32_t)__cvta_generic_to_shared(p);
}
__device__ __forceinline__ void cp_async16(uint32_t dst, const void* src, int src_size) {
    asm volatile("cp.async.cg.shared.global [%0], [%1], 16, %2;\n"
                 :: "r"(dst), "l"(src), "r"(src_size));
}
__device__ __forceinline__ void cp_commit() {
    asm volatile("cp.async.commit_group;\n" ::: "memory");
}
template <int N>
__device__ __forceinline__ void cp_wait() {
    asm volatile("cp.async.wait_group %0;\n" :: "n"(N) : "memory");
}

// ---------------------------------------------------------------------------
// Kernel 1: winner per pixel.  coors: [N,4] int32 (b, z, y, x)
// 4 voxels/thread; atomicMax result unused -> lowers to RED (no return trip).
// ---------------------------------------------------------------------------
__global__ void k_argmax_map(const int* __restrict__ coors, int n) {
    int i = (blockIdx.x * blockDim.x + threadIdx.x) * 4;
    #pragma unroll
    for (int m = 0; m < 4; m++) {
        int j = i + m;
        if (j < n) {
            int4 c = reinterpret_cast<const int4*>(coors)[j];
            atomicMax(&g_map[c.x * NYNX + c.z * NX + c.w], j + 1);
        }
    }
}

// ---------------------------------------------------------------------------
// Kernel 2: gather + transpose. 128-pixel x-tile, 4 stages through a
// 3-buffer cp.async ring: 64 warps/SM AND 2-3 read-stages always in flight
// behind each drain.
//   fill(0,1,2); s=0: wait<2>;drain;refill(3)  s=1: wait<2>  s=2: wait<1>
//   s=3: wait<0>
// Swizzle: P(xl, c) = xl*128 + ((c>>2 ^ xl) << 2) + (c&3), xl = x % 32.
//   Fill : warp=pixel, lane=quad -> cp.async 16B, conflict-free smem dst.
//   Drain: lane=x-in-stage, quad per item -> LDS.128 + 4x __stcs STG (128B
//   coalesced, evict-first: output is touch-once).
// ---------------------------------------------------------------------------
__device__ __forceinline__ void fill_stage(const float* __restrict__ feat,
                                           float* __restrict__ buf,
                                           const int* __restrict__ vidx,
                                           int s, int warp, int lane) {
    #pragma unroll
    for (int m = 0; m < 2; m++) {
        int xl = warp * 2 + m;                     // 0..31 within stage
        int v  = vidx[s * SPX + xl];
        uint32_t dst = smem_u32(&buf[xl * FEAT_DIM + ((lane ^ xl) << 2)]);
        const float* src = feat + (size_t)(v < 0 ? 0 : v) * FEAT_DIM + lane * 4;
        cp_async16(dst, src, v < 0 ? 0 : 16);      // zfill empties
    }
    cp_commit();
}

__device__ __forceinline__ void drain_stage(float* __restrict__ out,
                                            const float* __restrict__ buf,
                                            size_t pixbase, int s,
                                            int warp, int lane) {
    #pragma unroll
    for (int m = 0; m < 2; m++) {
        int q = warp * 2 + m;                      // channel quad 0..31
        float4 val = *reinterpret_cast<const float4*>(
            &buf[lane * FEAT_DIM + ((q ^ lane) << 2)]);     // LDS.128
        size_t o = pixbase + (size_t)(4 * q) * NYNX + s * SPX + lane;
        __stcs(out + o,            val.x);         // 4 x 128B coalesced STG
        __stcs(out + o +     NYNX, val.y);
        __stcs(out + o + 2 * NYNX, val.z);
        __stcs(out + o + 3 * NYNX, val.w);
    }
}

__global__ __launch_bounds__(NTH, 4)
void k_gather(const float* __restrict__ feat, float* __restrict__ out) {
    __shared__ float buf[NBUF][SPX * FEAT_DIM];    // 3 x 16 KB ring
    __shared__ int   vidx[XT];                     // 512 B

    int blk = blockIdx.x;              // 0 .. BATCH*NY*(NX/XT)-1
    int xt  = blk & (NX / XT - 1);     // 0..3
    int y   = (blk >> 2) & (NY - 1);   // 0..511
    int b   = blk >> 11;               // 0..3
    int x0  = xt * XT;

    int t = threadIdx.x, warp = t >> 5, lane = t & 31;

    if (t < XT) {
        int idx = b * NYNX + y * NX + x0 + t;
        int v = g_map[idx];
        vidx[t] = v - 1;               // -1 if empty
        if (v) g_map[idx] = 0;         // restore all-zero invariant
    }
    __syncthreads();

    // Prologue: fill stages 0..2 into ring slots 0..2
    #pragma unroll
    for (int s = 0; s < NBUF; s++)
        fill_stage(feat, buf[s], vidx, s, warp, lane);

    size_t pixbase = (size_t)b * FEAT_DIM * NYNX + (size_t)y * NX + x0;

    // s=0: groups pending {0,1,2}; need 0 -> wait<2>
    cp_wait<2>();
    __syncthreads();
    drain_stage(out, buf[0], pixbase, 0, warp, lane);
    __syncthreads();                               // slot 0 free
    fill_stage(feat, buf[0], vidx, 3, warp, lane); // stage 3 -> slot 0

    // s=1: pending {1,2,3}; need 1 -> wait<2>
    cp_wait<2>();
    __syncthreads();
    drain_stage(out, buf[1], pixbase, 1, warp, lane);

    // s=2: pending {2,3}; need 2 -> wait<1>
    cp_wait<1>();
    __syncthreads();
    drain_stage(out, buf[2], pixbase, 2, warp, lane);

    // s=3: pending {3}; -> wait<0>
    cp_wait<0>();
    __syncthreads();
    drain_stage(out, buf[0], pixbase, 3, warp, lane);
}

// ---------------------------------------------------------------------------
extern "C" void kernel_launch(void* const* d_in, const int* in_sizes, int n_in,
                              void* d_out, int out_size) {
    const float* feat  = (const float*)d_in[0];
    const int*   coors = (const int*)d_in[1];
    float*       out   = (float*)d_out;

    int n = in_sizes[0] / FEAT_DIM;   // number of voxels

    // 1) winner per pixel (map is all-zero by invariant)
    k_argmax_map<<<(n / 4 + 255) / 256, 256>>>(coors, n);
    // 2) gather + transpose full output (and restore map to zero)
    k_gather<<<BATCH * NY * (NX / XT), NTH>>>(feat, out);
}

// round 11
// speedup vs baseline: 1.0305x; 1.0152x over previous
#include <cuda_runtime.h>
#include <stdint.h>

// Problem constants (fixed by the reference problem definition)
#define FEAT_DIM 128
#define BATCH    4
#define NY       512
#define NX       512
#define NYNX     (NY * NX)
#define NPIX     (BATCH * NYNX)      // 1,048,576

#define XT    128      // x-tile per block (4 stages of 32)
#define SPX   32       // pixels per stage
#define NBUF  3        // ring buffers: smem ~50KB -> 4 blocks/SM = 64 warps
#define NTH   512      // 16 warps

// 4 MB scratch: winner map. INVARIANT: all-zero on entry to kernel_launch.
//  - zero at module load (device globals are zero-initialized)
//  - k_argmax writes (voxel_index + 1) via atomicMax (last-write-wins == max idx)
//  - k_gather restores every nonzero entry it consumed back to 0
__device__ int g_map[NPIX];

// ---------------------------------------------------------------------------
// cp.async helpers: 16B global->shared, src_size=0 => zero-fill (empty pixels)
// ---------------------------------------------------------------------------
__device__ __forceinline__ uint32_t smem_u32(const void* p) {
    return (uint32_t)__cvta_generic_to_shared(p);
}
__device__ __forceinline__ void cp_async16(uint32_t dst, const void* src, int src_size) {
    asm volatile("cp.async.cg.shared.global [%0], [%1], 16, %2;\n"
                 :: "r"(dst), "l"(src), "r"(src_size));
}
__device__ __forceinline__ void cp_commit() {
    asm volatile("cp.async.commit_group;\n" ::: "memory");
}
template <int N>
__device__ __forceinline__ void cp_wait() {
    asm volatile("cp.async.wait_group %0;\n" :: "n"(N) : "memory");
}

// ---------------------------------------------------------------------------
// Kernel 1: winner per pixel.  coors: [N,4] int32 (b, z, y, x)
// 2 voxels/thread (R8-proven fastest variant). Triggers PDL completion early.
// ---------------------------------------------------------------------------
__global__ void k_argmax_map(const int* __restrict__ coors, int n) {
    int i = (blockIdx.x * blockDim.x + threadIdx.x) * 2;
    if (i < n) {
        int4 c = reinterpret_cast<const int4*>(coors)[i];
        atomicMax(&g_map[c.x * NYNX + c.z * NX + c.w], i + 1);
    }
    if (i + 1 < n) {
        int4 c = reinterpret_cast<const int4*>(coors)[i + 1];
        atomicMax(&g_map[c.x * NYNX + c.z * NX + c.w], i + 2);
    }
    cudaTriggerProgrammaticLaunchCompletion();
}

// ---------------------------------------------------------------------------
// Kernel 2: gather + transpose (R10 plateau kernel: 113.2us, DRAM 73%).
// PDL: blocks become resident during k_argmax; cudaGridDependencySynchronize
// gates the g_map read, hiding launch + scheduling latency.
// 128-pixel x-tile, 4 stages through a 3-buffer cp.async ring.
// Swizzle: P(xl, c) = xl*128 + ((c>>2 ^ xl) << 2) + (c&3), xl = x % 32.
// ---------------------------------------------------------------------------
__device__ __forceinline__ void fill_stage(const float* __restrict__ feat,
                                           float* __restrict__ buf,
                                           const int* __restrict__ vidx,
                                           int s, int warp, int lane) {
    #pragma unroll
    for (int m = 0; m < 2; m++) {
        int xl = warp * 2 + m;                     // 0..31 within stage
        int v  = vidx[s * SPX + xl];
        uint32_t dst = smem_u32(&buf[xl * FEAT_DIM + ((lane ^ xl) << 2)]);
        const float* src = feat + (size_t)(v < 0 ? 0 : v) * FEAT_DIM + lane * 4;
        cp_async16(dst, src, v < 0 ? 0 : 16);      // zfill empties
    }
    cp_commit();
}

__device__ __forceinline__ void drain_stage(float* __restrict__ out,
                                            const float* __restrict__ buf,
                                            size_t pixbase, int s,
                                            int warp, int lane) {
    #pragma unroll
    for (int m = 0; m < 2; m++) {
        int q = warp * 2 + m;                      // channel quad 0..31
        float4 val = *reinterpret_cast<const float4*>(
            &buf[lane * FEAT_DIM + ((q ^ lane) << 2)]);     // LDS.128
        size_t o = pixbase + (size_t)(4 * q) * NYNX + s * SPX + lane;
        __stcs(out + o,            val.x);         // 4 x 128B coalesced STG
        __stcs(out + o +     NYNX, val.y);
        __stcs(out + o + 2 * NYNX, val.z);
        __stcs(out + o + 3 * NYNX, val.w);
    }
}

__global__ __launch_bounds__(NTH, 4)
void k_gather(const float* __restrict__ feat, float* __restrict__ out) {
    __shared__ float buf[NBUF][SPX * FEAT_DIM];    // 3 x 16 KB ring
    __shared__ int   vidx[XT];                     // 512 B

    int blk = blockIdx.x;              // 0 .. BATCH*NY*(NX/XT)-1
    int xt  = blk & (NX / XT - 1);     // 0..3
    int y   = (blk >> 2) & (NY - 1);   // 0..511
    int b   = blk >> 11;               // 0..3
    int x0  = xt * XT;

    int t = threadIdx.x, warp = t >> 5, lane = t & 31;

    // Wait for k_argmax to finish before touching g_map (PDL edge).
    cudaGridDependencySynchronize();

    if (t < XT) {
        int idx = b * NYNX + y * NX + x0 + t;
        int v = g_map[idx];
        vidx[t] = v - 1;               // -1 if empty
        if (v) g_map[idx] = 0;         // restore all-zero invariant
    }
    __syncthreads();

    // Prologue: fill stages 0..2 into ring slots 0..2
    #pragma unroll
    for (int s = 0; s < NBUF; s++)
        fill_stage(feat, buf[s], vidx, s, warp, lane);

    size_t pixbase = (size_t)b * FEAT_DIM * NYNX + (size_t)y * NX + x0;

    // s=0: groups pending {0,1,2}; need 0 -> wait<2>
    cp_wait<2>();
    __syncthreads();
    drain_stage(out, buf[0], pixbase, 0, warp, lane);
    __syncthreads();                               // slot 0 free
    fill_stage(feat, buf[0], vidx, 3, warp, lane); // stage 3 -> slot 0

    // s=1: pending {1,2,3}; need 1 -> wait<2>
    cp_wait<2>();
    __syncthreads();
    drain_stage(out, buf[1], pixbase, 1, warp, lane);

    // s=2: pending {2,3}; need 2 -> wait<1>
    cp_wait<1>();
    __syncthreads();
    drain_stage(out, buf[2], pixbase, 2, warp, lane);

    // s=3: pending {3}; -> wait<0>
    cp_wait<0>();
    __syncthreads();
    drain_stage(out, buf[0], pixbase, 3, warp, lane);
}

// ---------------------------------------------------------------------------
extern "C" void kernel_launch(void* const* d_in, const int* in_sizes, int n_in,
                              void* d_out, int out_size) {
    const float* feat  = (const float*)d_in[0];
    const int*   coors = (const int*)d_in[1];
    float*       out   = (float*)d_out;

    int n = in_sizes[0] / FEAT_DIM;   // number of voxels

    // 1) winner per pixel (map is all-zero by invariant)
    k_argmax_map<<<(n / 2 + 255) / 256, 256>>>(coors, n);

    // 2) gather, launched with PDL so its blocks spin up under k_argmax.
    cudaLaunchConfig_t cfg = {};
    cfg.gridDim  = dim3(BATCH * NY * (NX / XT));
    cfg.blockDim = dim3(NTH);
    cfg.stream   = 0;
    cudaLaunchAttribute attr[1];
    attr[0].id = cudaLaunchAttributeProgrammaticStreamSerialization;
    attr[0].val.programmaticStreamSerializationAllowed = 1;
    cfg.attrs    = attr;
    cfg.numAttrs = 1;
    cudaLaunchKernelEx(&cfg, k_gather, feat, out);
}